// round 6
// baseline (speedup 1.0000x reference)
#include <cuda_runtime.h>
#include <stdint.h>

// GCN: x3 = adj@(adj@(dropout(relu(adj@(x@W1)+b1)))@W2+b2)@W3+b3
// Inputs (metadata order): x[10000,1024], adj[10000,10000], W1[1024,512], b1[512],
//                          W2[512,256], b2[256], W3[256,128], b3[128]
// Output: [10000,128] fp32

#define N_NODES 10000

// Scratch (allocation-free: __device__ globals)
__device__ float g_T1[N_NODES * 512];
__device__ float g_X1[N_NODES * 512];
__device__ float g_T2[N_NODES * 256];
__device__ float g_X2[N_NODES * 256];
__device__ float g_T3[N_NODES * 128];

// ---------------------------------------------------------------------------
// JAX threefry2x32 dropout mask, PARTITIONABLE path (jax >= 0.5 default).
// key(42) -> (k0,k1) = (0,42).
// _threefry_random_bits_partitionable:
//   counts = iota_2x32_shape(shape)  -> (hi, lo) = (0, flat_idx)   [size < 2^32]
//   bits1, bits2 = threefry2x32_p.bind(k0, k1, hi, lo)
//   32-bit draw = bits1 ^ bits2        <-- this round's fix (XOR of both words)
// uniform u = bitcast((bits>>9)|0x3f800000)-1 ; keep = u<0.5 <=> bit31(bits)==0
// ---------------------------------------------------------------------------
__device__ __forceinline__ uint32_t rotl32(uint32_t x, int r) {
    return (x << r) | (x >> (32 - r));
}

__device__ __forceinline__ uint32_t dropout_bits(uint32_t idx) {
    const uint32_t k0 = 0u, k1 = 42u;
    const uint32_t k2 = k0 ^ k1 ^ 0x1BD11BDAu;
    uint32_t x0 = 0u + k0;      // counts_hi = 0
    uint32_t x1 = idx + k1;     // counts_lo = flat index
#define TF_R4(a,b,c,d) \
    x0 += x1; x1 = rotl32(x1,a); x1 ^= x0; \
    x0 += x1; x1 = rotl32(x1,b); x1 ^= x0; \
    x0 += x1; x1 = rotl32(x1,c); x1 ^= x0; \
    x0 += x1; x1 = rotl32(x1,d); x1 ^= x0;
    TF_R4(13,15,26,6);   x0 += k1; x1 += k2 + 1u;
    TF_R4(17,29,16,24);  x0 += k2; x1 += k0 + 2u;
    TF_R4(13,15,26,6);   x0 += k0; x1 += k1 + 3u;
    TF_R4(17,29,16,24);  x0 += k1; x1 += k2 + 4u;
    TF_R4(13,15,26,6);   x0 += k2; x1 += k0 + 5u;
#undef TF_R4
    return x0 ^ x1;   // partitionable 32-bit draw: XOR of the two output words
}

// ---------------------------------------------------------------------------
// Tiled fp32 GEMM: C[M,N] = A[M,K] @ B[K,N] (+epilogue)
// BM x 128 block tile, BK=8, 8x8 per thread, THREADS = BM*2.
// Requirements: N % 128 == 0, K % 8 == 0 (and %4 for float4). M may be ragged.
// EPI: 0 = none, 1 = +bias, 2 = +bias, relu, dropout(p=0.5, jax threefry key 42)
// ---------------------------------------------------------------------------
template<int BM, int EPI>
__global__ void __launch_bounds__(BM * 2)
gemm_kernel(const float* __restrict__ A, const float* __restrict__ B,
            const float* __restrict__ bias, float* __restrict__ C,
            int M, int N, int K)
{
    constexpr int BN = 128;
    constexpr int BK = 8;
    constexpr int THREADS = BM * 2;

    __shared__ float As[BK][BM];   // transposed: As[k][m]
    __shared__ float Bs[BK][BN];

    const int tid  = threadIdx.x;
    const int row0 = blockIdx.y * BM;
    const int col0 = blockIdx.x * BN;

    // per-thread 8x8 output tile coordinates
    const int tr = (tid >> 4) << 3;   // 0..BM-8 step 8
    const int tc = (tid & 15) << 3;   // 0..120 step 8

    float acc[8][8];
#pragma unroll
    for (int i = 0; i < 8; i++)
#pragma unroll
        for (int j = 0; j < 8; j++) acc[i][j] = 0.0f;

    for (int k0 = 0; k0 < K; k0 += BK) {
        // --- load A tile (BM x 8), zero-fill ragged M edge, store transposed
        {
            // BM*BK/4 = BM*2 float4 loads == THREADS -> exactly one per thread
            int r = tid >> 1;
            int c = (tid & 1) << 2;
            float4 v = make_float4(0.f, 0.f, 0.f, 0.f);
            if (row0 + r < M)
                v = *reinterpret_cast<const float4*>(A + (size_t)(row0 + r) * K + k0 + c);
            As[c + 0][r] = v.x;
            As[c + 1][r] = v.y;
            As[c + 2][r] = v.z;
            As[c + 3][r] = v.w;
        }
        // --- load B tile (8 x 128): BK*BN/4 = 256 float4 loads
#pragma unroll
        for (int t = tid; t < (BK * BN / 4); t += THREADS) {
            int r = t >> 5;
            int c = (t & 31) << 2;
            *reinterpret_cast<float4*>(&Bs[r][c]) =
                *reinterpret_cast<const float4*>(B + (size_t)(k0 + r) * N + col0 + c);
        }
        __syncthreads();

#pragma unroll
        for (int k = 0; k < BK; k++) {
            float4 a0 = *reinterpret_cast<float4*>(&As[k][tr]);
            float4 a1 = *reinterpret_cast<float4*>(&As[k][tr + 4]);
            float4 b0 = *reinterpret_cast<float4*>(&Bs[k][tc]);
            float4 b1 = *reinterpret_cast<float4*>(&Bs[k][tc + 4]);
            float ra[8] = {a0.x, a0.y, a0.z, a0.w, a1.x, a1.y, a1.z, a1.w};
            float rb[8] = {b0.x, b0.y, b0.z, b0.w, b1.x, b1.y, b1.z, b1.w};
#pragma unroll
            for (int i = 0; i < 8; i++)
#pragma unroll
                for (int j = 0; j < 8; j++)
                    acc[i][j] = fmaf(ra[i], rb[j], acc[i][j]);
        }
        __syncthreads();
    }

    // --- epilogue
#pragma unroll
    for (int i = 0; i < 8; i++) {
        int r = row0 + tr + i;
        if (r >= M) break;                 // rows are contiguous; safe
        size_t base = (size_t)r * N + col0 + tc;
#pragma unroll
        for (int j = 0; j < 8; j++) {
            int c = col0 + tc + j;
            float v = acc[i][j];
            if (EPI >= 1) v += bias[c];
            if (EPI == 2) {
                v = fmaxf(v, 0.0f);
                uint32_t idx  = (uint32_t)r * (uint32_t)N + (uint32_t)c;
                uint32_t bits = dropout_bits(idx);
                v = (bits & 0x80000000u) ? 0.0f : v * 2.0f;   // /(1-p), p=0.5
            }
            C[base + j] = v;
        }
    }
}

extern "C" void kernel_launch(void* const* d_in, const int* in_sizes, int n_in,
                              void* d_out, int out_size)
{
    const float* x   = (const float*)d_in[0];
    const float* adj = (const float*)d_in[1];
    const float* W1  = (const float*)d_in[2];
    const float* b1  = (const float*)d_in[3];
    const float* W2  = (const float*)d_in[4];
    const float* b2  = (const float*)d_in[5];
    const float* W3  = (const float*)d_in[6];
    const float* b3  = (const float*)d_in[7];
    float* out = (float*)d_out;

    float *T1, *X1, *T2, *X2, *T3;
    cudaGetSymbolAddress((void**)&T1, g_T1);
    cudaGetSymbolAddress((void**)&X1, g_X1);
    cudaGetSymbolAddress((void**)&T2, g_T2);
    cudaGetSymbolAddress((void**)&X2, g_X2);
    cudaGetSymbolAddress((void**)&T3, g_T3);

    const int M = N_NODES;
    const int gy128 = (M + 127) / 128;   // 79
    const int gy64  = (M + 63) / 64;     // 157

    // Layer 1: T1 = x @ W1 ; X1 = dropout(relu(adj @ T1 + b1))
    gemm_kernel<128, 0><<<dim3(512 / 128, gy128), 256>>>(x,   W1, nullptr, T1, M, 512, 1024);
    gemm_kernel<128, 2><<<dim3(512 / 128, gy128), 256>>>(adj, T1, b1,      X1, M, 512, M);

    // Layer 2: T2 = X1 @ W2 ; X2 = adj @ T2 + b2
    gemm_kernel<128, 0><<<dim3(256 / 128, gy128), 256>>>(X1,  W2, nullptr, T2, M, 256, 512);
    gemm_kernel<128, 1><<<dim3(256 / 128, gy128), 256>>>(adj, T2, b2,      X2, M, 256, M);

    // Layer 3: T3 = X2 @ W3 ; out = adj @ T3 + b3   (N=128 -> 64-row tiles, 157 CTAs)
    gemm_kernel<64, 0><<<dim3(128 / 128, gy64), 128>>>(X2,  W3, nullptr, T3, M, 128, 256);
    gemm_kernel<64, 1><<<dim3(128 / 128, gy64), 128>>>(adj, T3, b3,      out, M, 128, M);
}

// round 15
// speedup vs baseline: 2.1429x; 2.1429x over previous
#include <cuda_runtime.h>
#include <cuda_bf16.h>
#include <stdint.h>

// GCN via mma.sync (bf16x3 split) GEMMs — tcgen05 is rejected by this harness's
// compute_103 PTX target, so use the portable tensor-core path (HMMA).
// x3 = adj@(adj@(dropout(relu(adj@(x@W1)+b1)))@W2+b2)@W3+b3
// Inputs: x[10000,1024], adj[10000,10000], W1[1024,512], b1[512],
//         W2[512,256], b2[256], W3[256,128], b3[128]  -> out [10000,128] fp32

#define N_NODES 10000

// ---------------- scratch (__device__ globals; allocation-free) -------------
__device__ __nv_bfloat16 g_adj_hi[100000000];
__device__ __nv_bfloat16 g_adj_lo[100000000];
__device__ __nv_bfloat16 g_Ahi[10240000];   // reused: x, X1, X2 splits (A-side, [M,K])
__device__ __nv_bfloat16 g_Alo[10240000];
__device__ __nv_bfloat16 g_Bthi[5120000];   // reused: W1t,T1t,W2t,T2t,W3t,T3t (B-side, [N,K])
__device__ __nv_bfloat16 g_Btlo[5120000];
__device__ float g_T1[N_NODES * 512];
__device__ float g_X1[N_NODES * 512];
__device__ float g_T2[N_NODES * 256];
__device__ float g_X2[N_NODES * 256];
__device__ float g_T3[N_NODES * 128];

// ---------------- dropout: JAX partitionable threefry (verified R6) ---------
__device__ __forceinline__ uint32_t rotl32(uint32_t x, int r) {
    return (x << r) | (x >> (32 - r));
}
__device__ __forceinline__ uint32_t dropout_bits(uint32_t idx) {
    const uint32_t k0 = 0u, k1 = 42u;
    const uint32_t k2 = k0 ^ k1 ^ 0x1BD11BDAu;
    uint32_t x0 = 0u + k0;      // counts_hi = 0
    uint32_t x1 = idx + k1;     // counts_lo = flat index
#define TF_R4(a,b,c,d) \
    x0 += x1; x1 = rotl32(x1,a); x1 ^= x0; \
    x0 += x1; x1 = rotl32(x1,b); x1 ^= x0; \
    x0 += x1; x1 = rotl32(x1,c); x1 ^= x0; \
    x0 += x1; x1 = rotl32(x1,d); x1 ^= x0;
    TF_R4(13,15,26,6);   x0 += k1; x1 += k2 + 1u;
    TF_R4(17,29,16,24);  x0 += k2; x1 += k0 + 2u;
    TF_R4(13,15,26,6);   x0 += k0; x1 += k1 + 3u;
    TF_R4(17,29,16,24);  x0 += k1; x1 += k2 + 4u;
    TF_R4(13,15,26,6);   x0 += k2; x1 += k0 + 5u;
#undef TF_R4
    return x0 ^ x1;   // partitionable 32-bit draw: XOR of the two output words
}

// ---------------- PTX helpers ------------------------------------------------
__device__ __forceinline__ uint32_t smem_to_u32(const void* p) {
    uint32_t a;
    asm("{ .reg .u64 t; cvta.to.shared.u64 t, %1; cvt.u32.u64 %0, t; }" : "=r"(a) : "l"(p));
    return a;
}
#define CP16(dst, src, ok) \
    asm volatile("cp.async.cg.shared.global [%0], [%1], 16, %2;" \
        :: "r"(dst), "l"(src), "r"((ok) ? 16 : 0))
#define CP_COMMIT() asm volatile("cp.async.commit_group;" ::: "memory")
#define CP_WAIT0()  asm volatile("cp.async.wait_group 0;" ::: "memory")
#define CP_WAIT1()  asm volatile("cp.async.wait_group 1;" ::: "memory")
#define LDSM4(r, addr) \
    asm volatile("ldmatrix.sync.aligned.m8n8.x4.shared.b16 {%0,%1,%2,%3}, [%4];" \
        : "=r"((r)[0]), "=r"((r)[1]), "=r"((r)[2]), "=r"((r)[3]) : "r"(addr))
#define MMA_BF16(c, a, b0, b1) \
    asm volatile("mma.sync.aligned.m16n8k16.row.col.f32.bf16.bf16.f32 " \
        "{%0,%1,%2,%3}, {%4,%5,%6,%7}, {%8,%9}, {%0,%1,%2,%3};" \
        : "+f"((c)[0]), "+f"((c)[1]), "+f"((c)[2]), "+f"((c)[3]) \
        : "r"((a)[0]), "r"((a)[1]), "r"((a)[2]), "r"((a)[3]), "r"(b0), "r"(b1))

// ---------------- split kernels ---------------------------------------------
__global__ void asplit_kernel(const float* __restrict__ in,
                              __nv_bfloat16* __restrict__ ohi,
                              __nv_bfloat16* __restrict__ olo, size_t n)
{
    size_t g = (size_t)blockIdx.x * blockDim.x + threadIdx.x;
    if (g < n) {
        float v = in[g];
        __nv_bfloat16 h = __float2bfloat16(v);
        ohi[g] = h;
        olo[g] = __float2bfloat16(v - __bfloat162float(h));
    }
}

// in [R,C] fp32 -> out [C,R] bf16 hi/lo (transpose + split)
__global__ void tsplit_kernel(const float* __restrict__ in,
                              __nv_bfloat16* __restrict__ ohi,
                              __nv_bfloat16* __restrict__ olo, int R, int C)
{
    __shared__ float tile[32][33];
    int rb = blockIdx.x * 32, cb = blockIdx.y * 32;
    int x = threadIdx.x, y = threadIdx.y;
#pragma unroll
    for (int i = 0; i < 32; i += 8) {
        int r = rb + y + i, c = cb + x;
        tile[y + i][x] = (r < R && c < C) ? in[(size_t)r * C + c] : 0.0f;
    }
    __syncthreads();
#pragma unroll
    for (int i = 0; i < 32; i += 8) {
        int c = cb + y + i, r = rb + x;
        if (c < C && r < R) {
            float v = tile[x][y + i];
            __nv_bfloat16 h = __float2bfloat16(v);
            size_t o = (size_t)c * R + r;
            ohi[o] = h;
            olo[o] = __float2bfloat16(v - __bfloat162float(h));
        }
    }
}

// ---------------- mma.sync bf16x3 GEMM ---------------------------------------
// C[M,N] = (Ahi+Alo)[M,K] @ ((Bhi+Blo)[N,K])^T, fp32 accum.
// 128x128x32 tile, 256 threads, warp tile 64x32 (warp grid 2x4).
// Smem tiles padded to 80B rows (conflict-free ldmatrix). 2-stage cp.async.
// EPI: 0 none, 1 bias, 2 bias+relu+dropout.
#define TILE_B   10240            // 128 rows * 80 B
#define STAGE_B  (4 * TILE_B)     // Ahi, Alo, Bhi, Blo
#define SMEM_B   (2 * STAGE_B)    // 81920

template<int EPI>
__global__ void __launch_bounds__(256, 1)
mma_gemm(const __nv_bfloat16* __restrict__ Ahi, const __nv_bfloat16* __restrict__ Alo,
         const __nv_bfloat16* __restrict__ Bhi, const __nv_bfloat16* __restrict__ Blo,
         const float* __restrict__ bias, float* __restrict__ C,
         int M, int N, int K)
{
    extern __shared__ char smem[];
    const uint32_t sbase = smem_to_u32(smem);
    const int tid  = threadIdx.x;
    const int wid  = tid >> 5, lane = tid & 31;
    const int row0 = blockIdx.y * 128;
    const int col0 = blockIdx.x * 128;
    const int wr   = wid & 1;          // warp row: 0,1 -> m offset wr*64
    const int wc   = wid >> 1;         // warp col: 0..3 -> n offset wc*32

    // cp.async assignment: row = tid&127, chunks {tid>>7, (tid>>7)+2}
    const int cr  = tid & 127;
    const int cc0 = tid >> 7;
    const int rA  = row0 + cr;
    const bool rAok = rA < M;
    const size_t rAoff = (size_t)(rAok ? rA : 0) * K;
    const size_t rBoff = (size_t)(col0 + cr) * K;       // N % 128 == 0, always valid

    float acc[4][4][4];
#pragma unroll
    for (int mf = 0; mf < 4; mf++)
#pragma unroll
        for (int nf = 0; nf < 4; nf++)
#pragma unroll
            for (int e = 0; e < 4; e++) acc[mf][nf][e] = 0.0f;

    const int nchunks = (K + 31) / 32;

#define ISSUE(ci, st) do { \
    long kc_ = (long)(ci) * 32; \
    uint32_t sb_ = sbase + (st) * STAGE_B + cr * 80; \
    _Pragma("unroll") \
    for (int h_ = 0; h_ < 2; h_++) { \
        int c_ = cc0 + 2 * h_; \
        long kel_ = kc_ + c_ * 8; \
        bool kok_ = kel_ < K; \
        long ks_ = kok_ ? kel_ : 0; \
        uint32_t so_ = sb_ + c_ * 16; \
        CP16(so_,              Ahi + rAoff + ks_, rAok && kok_); \
        CP16(so_ + TILE_B,     Alo + rAoff + ks_, rAok && kok_); \
        CP16(so_ + 2 * TILE_B, Bhi + rBoff + ks_, kok_); \
        CP16(so_ + 3 * TILE_B, Blo + rBoff + ks_, kok_); \
    } \
} while (0)

    ISSUE(0, 0);
    CP_COMMIT();

    // ldmatrix lane addressing (conflict-free with 80B row pitch)
    const int arow = wr * 64 + (lane & 15);
    const int acol = 8 * (lane >> 4);
    const int brow = wc * 32 + (lane & 7) + ((lane >> 4) << 3);
    const int bcol = 8 * ((lane >> 3) & 1);

    for (int i = 0; i < nchunks; i++) {
        if (i + 1 < nchunks) {
            ISSUE(i + 1, (i + 1) & 1);
            CP_COMMIT();
            CP_WAIT1();
        } else {
            CP_WAIT0();
        }
        __syncthreads();

        const uint32_t sA = sbase + (i & 1) * STAGE_B;
#pragma unroll
        for (int ks = 0; ks < 2; ks++) {
            const int k0 = ks * 16;
            uint32_t ah[4][4], al[4][4], bhf[2][4], blf[2][4];
#pragma unroll
            for (int mf = 0; mf < 4; mf++) {
                uint32_t ad = sA + (arow + mf * 16) * 80 + (k0 + acol) * 2;
                LDSM4(ah[mf], ad);
                LDSM4(al[mf], ad + TILE_B);
            }
#pragma unroll
            for (int h = 0; h < 2; h++) {
                uint32_t bd = sA + 2 * TILE_B + (brow + h * 16) * 80 + (k0 + bcol) * 2;
                LDSM4(bhf[h], bd);
                LDSM4(blf[h], bd + TILE_B);
            }
#pragma unroll
            for (int mf = 0; mf < 4; mf++)
#pragma unroll
                for (int nf = 0; nf < 4; nf++) {
                    const uint32_t* bh2 = &bhf[nf >> 1][(nf & 1) * 2];
                    const uint32_t* bl2 = &blf[nf >> 1][(nf & 1) * 2];
                    MMA_BF16(acc[mf][nf], ah[mf], bh2[0], bh2[1]);
                    MMA_BF16(acc[mf][nf], ah[mf], bl2[0], bl2[1]);
                    MMA_BF16(acc[mf][nf], al[mf], bh2[0], bh2[1]);
                }
        }
        __syncthreads();
    }
#undef ISSUE

    // epilogue: c0,c1 -> row t/4, cols 2c,2c+1 ; c2,c3 -> row+8
#pragma unroll
    for (int mf = 0; mf < 4; mf++) {
        const int r_lo = row0 + wr * 64 + mf * 16 + (lane >> 2);
#pragma unroll
        for (int half = 0; half < 2; half++) {
            const int r = r_lo + half * 8;
            if (r < M) {
#pragma unroll
                for (int nf = 0; nf < 4; nf++) {
                    const int gc = col0 + wc * 32 + nf * 8 + (lane & 3) * 2;
                    float v0 = acc[mf][nf][half * 2 + 0];
                    float v1 = acc[mf][nf][half * 2 + 1];
                    if (EPI >= 1) { v0 += bias[gc]; v1 += bias[gc + 1]; }
                    if (EPI == 2) {
                        v0 = fmaxf(v0, 0.0f);
                        v1 = fmaxf(v1, 0.0f);
                        uint32_t i0 = (uint32_t)r * (uint32_t)N + (uint32_t)gc;
                        v0 = (dropout_bits(i0)     & 0x80000000u) ? 0.0f : v0 * 2.0f;
                        v1 = (dropout_bits(i0 + 1) & 0x80000000u) ? 0.0f : v1 * 2.0f;
                    }
                    *reinterpret_cast<float2*>(C + (size_t)r * N + gc) = make_float2(v0, v1);
                }
            }
        }
    }
}

// ---------------- host orchestration ----------------------------------------
extern "C" void kernel_launch(void* const* d_in, const int* in_sizes, int n_in,
                              void* d_out, int out_size)
{
    const float* x   = (const float*)d_in[0];
    const float* adj = (const float*)d_in[1];
    const float* W1  = (const float*)d_in[2];
    const float* b1  = (const float*)d_in[3];
    const float* W2  = (const float*)d_in[4];
    const float* b2  = (const float*)d_in[5];
    const float* W3  = (const float*)d_in[6];
    const float* b3  = (const float*)d_in[7];
    float* out = (float*)d_out;

    __nv_bfloat16 *adjh, *adjl, *Ah, *Al, *Bth, *Btl;
    float *T1, *X1, *T2, *X2, *T3;
    cudaGetSymbolAddress((void**)&adjh, g_adj_hi);
    cudaGetSymbolAddress((void**)&adjl, g_adj_lo);
    cudaGetSymbolAddress((void**)&Ah, g_Ahi);
    cudaGetSymbolAddress((void**)&Al, g_Alo);
    cudaGetSymbolAddress((void**)&Bth, g_Bthi);
    cudaGetSymbolAddress((void**)&Btl, g_Btlo);
    cudaGetSymbolAddress((void**)&T1, g_T1);
    cudaGetSymbolAddress((void**)&X1, g_X1);
    cudaGetSymbolAddress((void**)&T2, g_T2);
    cudaGetSymbolAddress((void**)&X2, g_X2);
    cudaGetSymbolAddress((void**)&T3, g_T3);

    cudaFuncSetAttribute(mma_gemm<0>, cudaFuncAttributeMaxDynamicSharedMemorySize, SMEM_B);
    cudaFuncSetAttribute(mma_gemm<1>, cudaFuncAttributeMaxDynamicSharedMemorySize, SMEM_B);
    cudaFuncSetAttribute(mma_gemm<2>, cudaFuncAttributeMaxDynamicSharedMemorySize, SMEM_B);

    const int M = N_NODES;
    const int gy = (M + 127) / 128;          // 79
    dim3 tsb(32, 8);
    auto tsg = [](int R, int C) { return dim3((R + 31) / 32, (C + 31) / 32); };

    // one-time splits
    asplit_kernel<<<(100000000u + 255) / 256, 256>>>(adj, adjh, adjl, (size_t)M * M);
    asplit_kernel<<<(10240000u + 255) / 256, 256>>>(x, Ah, Al, (size_t)M * 1024);

    // Layer 1
    tsplit_kernel<<<tsg(1024, 512), tsb>>>(W1, Bth, Btl, 1024, 512);
    mma_gemm<0><<<dim3(4, gy), 256, SMEM_B>>>(Ah, Al, Bth, Btl, nullptr, T1, M, 512, 1024);
    tsplit_kernel<<<tsg(M, 512), tsb>>>(T1, Bth, Btl, M, 512);
    mma_gemm<2><<<dim3(4, gy), 256, SMEM_B>>>(adjh, adjl, Bth, Btl, b1, X1, M, 512, M);

    // Layer 2
    asplit_kernel<<<((unsigned)(M * 512) + 255) / 256, 256>>>(X1, Ah, Al, (size_t)M * 512);
    tsplit_kernel<<<tsg(512, 256), tsb>>>(W2, Bth, Btl, 512, 256);
    mma_gemm<0><<<dim3(2, gy), 256, SMEM_B>>>(Ah, Al, Bth, Btl, nullptr, T2, M, 256, 512);
    tsplit_kernel<<<tsg(M, 256), tsb>>>(T2, Bth, Btl, M, 256);
    mma_gemm<1><<<dim3(2, gy), 256, SMEM_B>>>(adjh, adjl, Bth, Btl, b2, X2, M, 256, M);

    // Layer 3
    asplit_kernel<<<((unsigned)(M * 256) + 255) / 256, 256>>>(X2, Ah, Al, (size_t)M * 256);
    tsplit_kernel<<<tsg(256, 128), tsb>>>(W3, Bth, Btl, 256, 128);
    mma_gemm<0><<<dim3(1, gy), 256, SMEM_B>>>(Ah, Al, Bth, Btl, nullptr, T3, M, 128, 256);
    tsplit_kernel<<<tsg(M, 128), tsb>>>(T3, Bth, Btl, M, 128);
    mma_gemm<1><<<dim3(1, gy), 256, SMEM_B>>>(adjh, adjl, Bth, Btl, b3, out, M, 128, M);
}